// round 3
// baseline (speedup 1.0000x reference)
#include <cuda_runtime.h>

// SSIM loss, fused separable 11x11 Gaussian, B=16 C=3 H=512 W=512 fp32.
// Layout: grid = (8 row-chunks, 48 planes), block = 128 threads, 4 cols/thread.
// Vertical conv from a register-resident 11-row ring of raw sr/hr values,
// horizontal conv via a small padded smem buffer, block-reduced into a
// double accumulator, finalized by a tiny kernel.

#define HH 512
#define WW 512
#define NPLANES 48
#define TH 64            // output rows per block
#define NTHREADS 128
#define NPIX 12582912.0  // 16*3*512*512

// Gaussian(window=11, sigma=1.5), normalized. Hardcoded as literals so ptxas
// emits FFMA/FMUL with immediate operand (rt_SMSP = 1, double throughput).
__device__ constexpr float KW[11] = {
    0.00102839f, 0.00759876f, 0.03600077f, 0.10936069f, 0.21300554f,
    0.26601172f,
    0.21300554f, 0.10936069f, 0.03600077f, 0.00759876f, 0.00102839f};

__device__ double g_accum;

__device__ __forceinline__ void load_row(const float* __restrict__ p, int row,
                                         int c0, float out[4]) {
    if ((unsigned)row < (unsigned)HH) {
        float4 v = *reinterpret_cast<const float4*>(p + row * WW + c0);
        out[0] = v.x; out[1] = v.y; out[2] = v.z; out[3] = v.w;
    } else {
        out[0] = 0.f; out[1] = 0.f; out[2] = 0.f; out[3] = 0.f;
    }
}

__global__ void zero_kernel() { g_accum = 0.0; }

__global__ void finalize_kernel(float* out) {
    out[0] = (float)(1.0 - g_accum / NPIX);
}

__global__ __launch_bounds__(NTHREADS, 3)
void ssim_kernel(const float* __restrict__ sr, const float* __restrict__ hr) {
    const int plane = blockIdx.y;
    const int r0 = blockIdx.x * TH;
    const int tid = threadIdx.x;
    const int c0 = tid * 4;  // this thread's 4 output columns

    const float* __restrict__ pa = sr + (size_t)plane * HH * WW;
    const float* __restrict__ pb = hr + (size_t)plane * HH * WW;

    // vs buffer: 5 fields, data col c at word index c+8 (writes 16B-aligned),
    // halo zeros at words [3..7] (cols -5..-1) and [520..527] (cols 512..516+pad).
    __shared__ __align__(16) float vsbuf[5][528];

    // init halo zeros (words 0..7 and 520..527 per field)
    if (tid < 80) {
        int f = tid >> 4;
        int k = tid & 15;
        int idx = (k < 8) ? k : (512 + k);
        vsbuf[f][idx] = 0.f;
    }
    __syncthreads();

    // Register ring of raw input rows: after each load, ra/rb[0..10] hold the
    // last 11 loaded rows (rows ir-10 .. ir).
    float ra[11][4], rb[11][4];
    float na[4], nb[4];  // prefetched next row

#pragma unroll
    for (int k = 0; k < 10; ++k) {
        load_row(pa, r0 - 5 + k, c0, ra[k + 1]);
        load_row(pb, r0 - 5 + k, c0, rb[k + 1]);
    }
    // prefetch the first mainloop row
    load_row(pa, r0 + 5, c0, na);
    load_row(pb, r0 + 5, c0, nb);

    float acc = 0.f;

#pragma unroll 4
    for (int i = 0; i < TH; ++i) {
        // shift ring down by one row
#pragma unroll
        for (int k = 0; k < 10; ++k) {
#pragma unroll
            for (int j = 0; j < 4; ++j) {
                ra[k][j] = ra[k + 1][j];
                rb[k][j] = rb[k + 1][j];
            }
        }
        // consume prefetched row, prefetch the next one
#pragma unroll
        for (int j = 0; j < 4; ++j) { ra[10][j] = na[j]; rb[10][j] = nb[j]; }
        load_row(pa, r0 + 6 + i, c0, na);
        load_row(pb, r0 + 6 + i, c0, nb);

        // vertical 11-tap conv of the 5 product fields (registers only)
        float vs[5][4];
#pragma unroll
        for (int j = 0; j < 4; ++j) {
            float s0 = 0.f, s1 = 0.f, s2 = 0.f, s3 = 0.f, s4 = 0.f;
#pragma unroll
            for (int k = 0; k < 11; ++k) {
                float a = ra[k][j];
                float b = rb[k][j];
                float wa = KW[k] * a;   // FMUL-imm
                float wb = KW[k] * b;   // FMUL-imm
                s0 += wa;
                s1 += wb;
                s2 += wa * a;
                s3 += wb * b;
                s4 += wa * b;
            }
            vs[0][j] = s0; vs[1][j] = s1; vs[2][j] = s2;
            vs[3][j] = s3; vs[4][j] = s4;
        }

        // publish vertical sums (aligned STS.128 per field)
#pragma unroll
        for (int f = 0; f < 5; ++f) {
            *reinterpret_cast<float4*>(&vsbuf[f][8 + c0]) =
                make_float4(vs[f][0], vs[f][1], vs[f][2], vs[f][3]);
        }
        __syncthreads();

        // horizontal 11-tap conv per field, 4 outputs per thread.
        // window for output col c0+j is words (8+c0+j-5) .. (8+c0+j+5)
        // = [c0+3 .. c0+16] -> covered by 5 aligned LDS.128 at c0 .. c0+16.
        float cv[5][4];
#pragma unroll
        for (int f = 0; f < 5; ++f) {
            float v[20];
#pragma unroll
            for (int q = 0; q < 5; ++q) {
                float4 t = *reinterpret_cast<const float4*>(&vsbuf[f][c0 + 4 * q]);
                v[4 * q + 0] = t.x; v[4 * q + 1] = t.y;
                v[4 * q + 2] = t.z; v[4 * q + 3] = t.w;
            }
#pragma unroll
            for (int j = 0; j < 4; ++j) {
                float s = 0.f;
#pragma unroll
                for (int k = 0; k < 11; ++k) s += KW[k] * v[3 + j + k];  // FFMA-imm
                cv[f][j] = s;
            }
        }
        __syncthreads();  // protect vsbuf before next iteration's writes

        // SSIM map + accumulate
#pragma unroll
        for (int j = 0; j < 4; ++j) {
            float m1 = cv[0][j], m2 = cv[1][j];
            float e11 = cv[2][j], e22 = cv[3][j], e12 = cv[4][j];
            float m1s = m1 * m1;
            float m2s = m2 * m2;
            float m12 = m1 * m2;
            float num = (2.f * m12 + 1e-4f) * (2.f * (e12 - m12) + 9e-4f);
            float den = (m1s + m2s + 1e-4f) *
                            ((e11 - m1s) + (e22 - m2s) + 9e-4f) +
                        1e-12f;
            acc += __fdividef(num, den);
        }
    }

    // block reduction
#pragma unroll
    for (int o = 16; o > 0; o >>= 1)
        acc += __shfl_down_sync(0xFFFFFFFFu, acc, o);

    __shared__ float wsum[4];
    if ((tid & 31) == 0) wsum[tid >> 5] = acc;
    __syncthreads();
    if (tid == 0) {
        double s = (double)wsum[0] + (double)wsum[1] + (double)wsum[2] +
                   (double)wsum[3];
        atomicAdd(&g_accum, s);
    }
}

extern "C" void kernel_launch(void* const* d_in, const int* in_sizes, int n_in,
                              void* d_out, int out_size) {
    const float* sr = (const float*)d_in[0];
    const float* hr = (const float*)d_in[1];
    float* out = (float*)d_out;

    zero_kernel<<<1, 1>>>();
    dim3 grid(HH / TH, NPLANES);
    ssim_kernel<<<grid, NTHREADS>>>(sr, hr);
    finalize_kernel<<<1, 1>>>(out);
}

// round 4
// speedup vs baseline: 1.0921x; 1.0921x over previous
#include <cuda_runtime.h>

// SSIM loss, fused separable 11x11 Gaussian, B=16 C=3 H=512 W=512 fp32.
// grid = (8 row-chunks, 48 planes), 128 threads, 4 cols/thread (2 f32x2 packs).
// Vertical conv: register ring of packed raw rows, f32x2 accumulation.
// Fields reduced to 4: mu1, mu2, conv(a^2+b^2), conv(ab).
// Horizontal conv: scalar FFMA-imm (rt=1) from double-buffered padded smem.
// Per-block partials (no atomics, no zero kernel) reduced by finalize kernel.

#define HH 512
#define WW 512
#define TH 64
#define NTHREADS 128
#define NPIX 12582912.0
#define GX 8
#define GY 48
#define NBLOCKS (GX * GY)

typedef unsigned long long u64;

__device__ constexpr float KW[11] = {
    0.00102839f, 0.00759876f, 0.03600077f, 0.10936069f, 0.21300554f,
    0.26601172f,
    0.21300554f, 0.10936069f, 0.03600077f, 0.00759876f, 0.00102839f};

__device__ double g_partial[NBLOCKS];

// ---- f32x2 packed helpers (sm_100+ PTX) ----
__device__ __forceinline__ u64 pk2(float lo, float hi) {
    u64 r; asm("mov.b64 %0, {%1, %2};" : "=l"(r) : "f"(lo), "f"(hi)); return r;
}
__device__ __forceinline__ void upk2(u64 v, float& lo, float& hi) {
    asm("mov.b64 {%0, %1}, %2;" : "=f"(lo), "=f"(hi) : "l"(v));
}
__device__ __forceinline__ u64 f2add(u64 a, u64 b) {
    u64 r; asm("add.rn.f32x2 %0, %1, %2;" : "=l"(r) : "l"(a), "l"(b)); return r;
}
__device__ __forceinline__ u64 f2mul(u64 a, u64 b) {
    u64 r; asm("mul.rn.f32x2 %0, %1, %2;" : "=l"(r) : "l"(a), "l"(b)); return r;
}
__device__ __forceinline__ u64 f2fma(u64 a, u64 b, u64 c) {
    u64 r; asm("fma.rn.f32x2 %0, %1, %2, %3;" : "=l"(r) : "l"(a), "l"(b), "l"(c));
    return r;
}
// a - b with a single rounding via fma(b, -1, a)
__device__ __forceinline__ u64 f2sub(u64 a, u64 b, u64 neg1) {
    return f2fma(b, neg1, a);
}

__device__ __forceinline__ void load_row_pk(const float* __restrict__ p,
                                            int row, int c0, u64 o[2]) {
    if ((unsigned)row < (unsigned)HH) {
        ulonglong2 v = *reinterpret_cast<const ulonglong2*>(p + row * WW + c0);
        o[0] = v.x;  // cols (c0, c0+1)
        o[1] = v.y;  // cols (c0+2, c0+3)
    } else {
        o[0] = 0ull; o[1] = 0ull;
    }
}

__global__ void finalize_kernel(float* out) {
    int t = threadIdx.x;
    double s = 0.0;
    for (int i = t; i < NBLOCKS; i += 128) s += g_partial[i];
#pragma unroll
    for (int o = 16; o > 0; o >>= 1) s += __shfl_down_sync(0xFFFFFFFFu, s, o);
    __shared__ double sm[4];
    if ((t & 31) == 0) sm[t >> 5] = s;
    __syncthreads();
    if (t == 0) {
        double tot = sm[0] + sm[1] + sm[2] + sm[3];
        out[0] = (float)(1.0 - tot / NPIX);
    }
}

__global__ __launch_bounds__(NTHREADS, 3)
void ssim_kernel(const float* __restrict__ sr, const float* __restrict__ hr) {
    const int plane = blockIdx.y;
    const int r0 = blockIdx.x * TH;
    const int tid = threadIdx.x;
    const int c0 = tid * 4;

    const float* __restrict__ pa = sr + (size_t)plane * HH * WW;
    const float* __restrict__ pb = hr + (size_t)plane * HH * WW;

    // Double-buffered line buffer: 4 fields, data col c at word c+8,
    // halo zeros at words [0..7] and [520..527].
    __shared__ __align__(16) float vsbuf[2][4][528];

    if (tid < 128) {
        int b = tid >> 6;
        int f = (tid >> 4) & 3;
        int k = tid & 15;
        int idx = (k < 8) ? k : (512 + k);
        vsbuf[b][f][idx] = 0.f;
    }
    __syncthreads();

    // Register ring of packed raw rows (last 11 loaded rows).
    u64 ra[11][2], rb[11][2], na[2], nb[2];
#pragma unroll
    for (int k = 0; k < 10; ++k) {
        load_row_pk(pa, r0 - 5 + k, c0, ra[k + 1]);
        load_row_pk(pb, r0 - 5 + k, c0, rb[k + 1]);
    }
    load_row_pk(pa, r0 + 5, c0, na);
    load_row_pk(pb, r0 + 5, c0, nb);

    const u64 TWO  = pk2(2.f, 2.f);
    const u64 NEG1 = pk2(-1.f, -1.f);
    const u64 C1   = pk2(1e-4f, 1e-4f);
    const u64 C2   = pk2(9e-4f, 9e-4f);
    const u64 EPS  = pk2(1e-12f, 1e-12f);

    float acc = 0.f;

#pragma unroll 4
    for (int i = 0; i < TH; ++i) {
        const int buf = i & 1;

        // shift ring, consume prefetch, prefetch next row
#pragma unroll
        for (int k = 0; k < 10; ++k) {
#pragma unroll
            for (int p = 0; p < 2; ++p) {
                ra[k][p] = ra[k + 1][p];
                rb[k][p] = rb[k + 1][p];
            }
        }
#pragma unroll
        for (int p = 0; p < 2; ++p) { ra[10][p] = na[p]; rb[10][p] = nb[p]; }
        load_row_pk(pa, r0 + 6 + i, c0, na);
        load_row_pk(pb, r0 + 6 + i, c0, nb);

        // vertical 11-tap conv, packed. Fields: m1, m2, q=a^2+b^2, r=ab.
        // Split q accumulator to halve the dependency chain.
        u64 s0[2], s1[2], sqa[2], sqb[2], srr[2];
#pragma unroll
        for (int p = 0; p < 2; ++p) {
            s0[p] = 0ull; s1[p] = 0ull; sqa[p] = 0ull; sqb[p] = 0ull;
            srr[p] = 0ull;
        }
#pragma unroll
        for (int k = 0; k < 11; ++k) {
#pragma unroll
            for (int p = 0; p < 2; ++p) {
                u64 a = ra[k][p], b = rb[k][p];
                float alo, ahi, blo, bhi;
                upk2(a, alo, ahi);
                upk2(b, blo, bhi);
                u64 wa = pk2(KW[k] * alo, KW[k] * ahi);  // 2x FMUL-imm (rt=1)
                u64 wb = pk2(KW[k] * blo, KW[k] * bhi);
                s0[p]  = f2add(s0[p], wa);
                s1[p]  = f2add(s1[p], wb);
                sqa[p] = f2fma(wa, a, sqa[p]);
                sqb[p] = f2fma(wb, b, sqb[p]);
                srr[p] = f2fma(wa, b, srr[p]);
            }
        }

        // publish vertical sums: one STS.128 per field (two packed halves)
        {
            ulonglong2 t;
            t.x = s0[0]; t.y = s0[1];
            *reinterpret_cast<ulonglong2*>(&vsbuf[buf][0][8 + c0]) = t;
            t.x = s1[0]; t.y = s1[1];
            *reinterpret_cast<ulonglong2*>(&vsbuf[buf][1][8 + c0]) = t;
            t.x = f2add(sqa[0], sqb[0]); t.y = f2add(sqa[1], sqb[1]);
            *reinterpret_cast<ulonglong2*>(&vsbuf[buf][2][8 + c0]) = t;
            t.x = srr[0]; t.y = srr[1];
            *reinterpret_cast<ulonglong2*>(&vsbuf[buf][3][8 + c0]) = t;
        }
        __syncthreads();  // single barrier per iter (double-buffered)

        // horizontal 11-tap conv per field, scalar FFMA-imm (rt=1).
        float cv[4][4];
#pragma unroll
        for (int f = 0; f < 4; ++f) {
            float v[20];
#pragma unroll
            for (int q = 0; q < 5; ++q) {
                float4 t = *reinterpret_cast<const float4*>(
                    &vsbuf[buf][f][c0 + 4 * q]);
                v[4 * q + 0] = t.x; v[4 * q + 1] = t.y;
                v[4 * q + 2] = t.z; v[4 * q + 3] = t.w;
            }
#pragma unroll
            for (int j = 0; j < 4; ++j) {
                float s = 0.f;
#pragma unroll
                for (int k = 0; k < 11; ++k) s += KW[k] * v[3 + j + k];
                cv[f][j] = s;
            }
        }

        // SSIM map, packed (2 cols per pack)
#pragma unroll
        for (int p = 0; p < 2; ++p) {
            u64 m1 = pk2(cv[0][2 * p], cv[0][2 * p + 1]);
            u64 m2 = pk2(cv[1][2 * p], cv[1][2 * p + 1]);
            u64 qq = pk2(cv[2][2 * p], cv[2][2 * p + 1]);
            u64 rr = pk2(cv[3][2 * p], cv[3][2 * p + 1]);

            u64 m12 = f2mul(m1, m2);
            u64 sms = f2fma(m2, m2, f2mul(m1, m1));      // m1^2 + m2^2
            u64 num1 = f2fma(TWO, m12, C1);              // 2*m12 + c1
            u64 sig12 = f2sub(rr, m12, NEG1);            // r - m12
            u64 num2 = f2fma(TWO, sig12, C2);            // 2*sig12 + c2
            u64 den1 = f2add(sms, C1);
            u64 den2 = f2add(f2sub(qq, sms, NEG1), C2);  // q - sms + c2
            u64 num = f2mul(num1, num2);
            u64 den = f2fma(den1, den2, EPS);

            float n0, n1, d0, d1;
            upk2(num, n0, n1);
            upk2(den, d0, d1);
            acc += __fdividef(n0, d0);
            acc += __fdividef(n1, d1);
        }
    }

    // block reduction -> per-block partial (no atomics, no zeroing needed)
#pragma unroll
    for (int o = 16; o > 0; o >>= 1)
        acc += __shfl_down_sync(0xFFFFFFFFu, acc, o);

    __shared__ float wsum[4];
    if ((tid & 31) == 0) wsum[tid >> 5] = acc;
    __syncthreads();
    if (tid == 0) {
        double s = (double)wsum[0] + (double)wsum[1] + (double)wsum[2] +
                   (double)wsum[3];
        g_partial[blockIdx.y * GX + blockIdx.x] = s;
    }
}

extern "C" void kernel_launch(void* const* d_in, const int* in_sizes, int n_in,
                              void* d_out, int out_size) {
    const float* sr = (const float*)d_in[0];
    const float* hr = (const float*)d_in[1];
    float* out = (float*)d_out;

    dim3 grid(GX, GY);
    ssim_kernel<<<grid, NTHREADS>>>(sr, hr);
    finalize_kernel<<<1, 128>>>(out);
}

// round 5
// speedup vs baseline: 1.1722x; 1.0733x over previous
#include <cuda_runtime.h>

// SSIM loss, fused separable 11x11 Gaussian, B=16 C=3 H=512 W=512 fp32.
// grid = (8 row-chunks, 48 planes), 128 threads, 4 cols/thread (2 f32x2 packs).
// Vertical conv: register ring of packed raw rows, f32x2 math with PACKED
// weight constants (no pk/upk movs). Fields: mu1, mu2, conv(a^2+b^2), conv(ab).
// Horizontal conv: scalar FFMA-imm, own 4 cols from registers, 8-word halos
// from double-buffered padded smem (4 LDS.128/field).
// Finalization folded into the last block (atomicInc wrap, graph-replay safe).

#define HH 512
#define WW 512
#define TH 64
#define NTHREADS 128
#define NPIX 12582912.0
#define GX 8
#define GY 48
#define NBLOCKS (GX * GY)

typedef unsigned long long u64;

__device__ constexpr float KW[11] = {
    0.00102839f, 0.00759876f, 0.03600077f, 0.10936069f, 0.21300554f,
    0.26601172f,
    0.21300554f, 0.10936069f, 0.03600077f, 0.00759876f, 0.00102839f};

__device__ double g_partial[NBLOCKS];
__device__ unsigned g_count = 0;

// ---- f32x2 packed helpers (sm_100+ PTX) ----
__device__ __forceinline__ u64 pk2(float lo, float hi) {
    u64 r; asm("mov.b64 %0, {%1, %2};" : "=l"(r) : "f"(lo), "f"(hi)); return r;
}
__device__ __forceinline__ void upk2(u64 v, float& lo, float& hi) {
    asm("mov.b64 {%0, %1}, %2;" : "=f"(lo), "=f"(hi) : "l"(v));
}
__device__ __forceinline__ u64 f2add(u64 a, u64 b) {
    u64 r; asm("add.rn.f32x2 %0, %1, %2;" : "=l"(r) : "l"(a), "l"(b)); return r;
}
__device__ __forceinline__ u64 f2mul(u64 a, u64 b) {
    u64 r; asm("mul.rn.f32x2 %0, %1, %2;" : "=l"(r) : "l"(a), "l"(b)); return r;
}
__device__ __forceinline__ u64 f2fma(u64 a, u64 b, u64 c) {
    u64 r; asm("fma.rn.f32x2 %0, %1, %2, %3;" : "=l"(r) : "l"(a), "l"(b), "l"(c));
    return r;
}

__device__ __forceinline__ void load_row_pk(const float* __restrict__ p,
                                            int row, int c0, u64 o[2]) {
    if ((unsigned)row < (unsigned)HH) {
        ulonglong2 v = *reinterpret_cast<const ulonglong2*>(p + row * WW + c0);
        o[0] = v.x;
        o[1] = v.y;
    } else {
        o[0] = 0ull; o[1] = 0ull;
    }
}

__global__ __launch_bounds__(NTHREADS, 3)
void ssim_kernel(const float* __restrict__ sr, const float* __restrict__ hr,
                 float* __restrict__ out) {
    const int plane = blockIdx.y;
    const int r0 = blockIdx.x * TH;
    const int tid = threadIdx.x;
    const int c0 = tid * 4;

    const float* __restrict__ pa = sr + (size_t)plane * HH * WW;
    const float* __restrict__ pb = hr + (size_t)plane * HH * WW;

    // Double-buffered line buffer: 4 fields, data col c at word c+8,
    // halo zeros at words [0..7] and [520..527].
    __shared__ __align__(16) float vsbuf[2][4][528];

    {
        int b = tid >> 6;
        int f = (tid >> 4) & 3;
        int k = tid & 15;
        int idx = (k < 8) ? k : (512 + k);
        vsbuf[b][f][idx] = 0.f;
    }
    __syncthreads();

    // Packed weight constants (symmetric kernel -> 6 uniques).
    u64 WKP[6];
#pragma unroll
    for (int k = 0; k < 6; ++k) WKP[k] = pk2(KW[k], KW[k]);

    // Register ring of packed raw rows (last 11 loaded rows).
    u64 ra[11][2], rb[11][2], na[2], nb[2];
#pragma unroll
    for (int k = 0; k < 10; ++k) {
        load_row_pk(pa, r0 - 5 + k, c0, ra[k + 1]);
        load_row_pk(pb, r0 - 5 + k, c0, rb[k + 1]);
    }
    load_row_pk(pa, r0 + 5, c0, na);
    load_row_pk(pb, r0 + 5, c0, nb);

    const u64 TWO  = pk2(2.f, 2.f);
    const u64 NEG1 = pk2(-1.f, -1.f);
    const u64 C1   = pk2(1e-4f, 1e-4f);
    const u64 C2   = pk2(9e-4f, 9e-4f);

    float acc = 0.f;

#pragma unroll 4
    for (int i = 0; i < TH; ++i) {
        const int buf = i & 1;

        // shift ring, consume prefetch, prefetch next row
#pragma unroll
        for (int k = 0; k < 10; ++k) {
#pragma unroll
            for (int p = 0; p < 2; ++p) {
                ra[k][p] = ra[k + 1][p];
                rb[k][p] = rb[k + 1][p];
            }
        }
#pragma unroll
        for (int p = 0; p < 2; ++p) { ra[10][p] = na[p]; rb[10][p] = nb[p]; }
        load_row_pk(pa, r0 + 6 + i, c0, na);
        load_row_pk(pb, r0 + 6 + i, c0, nb);

        // vertical 11-tap conv, fully packed. Center tap initializes.
        u64 s0[2], s1[2], sqa[2], sqb[2], sr4[2];
#pragma unroll
        for (int p = 0; p < 2; ++p) {
            u64 a = ra[5][p], b = rb[5][p];
            u64 wa = f2mul(WKP[5], a);
            u64 wb = f2mul(WKP[5], b);
            s0[p] = wa;
            s1[p] = wb;
            sqa[p] = f2mul(wa, a);
            sqb[p] = f2mul(wb, b);
            sr4[p] = f2mul(wa, b);
        }
#pragma unroll
        for (int k = 0; k < 11; ++k) {
            if (k == 5) continue;
            const int wi = (k < 5) ? k : (10 - k);
#pragma unroll
            for (int p = 0; p < 2; ++p) {
                u64 a = ra[k][p], b = rb[k][p];
                u64 wa = f2mul(WKP[wi], a);
                u64 wb = f2mul(WKP[wi], b);
                s0[p]  = f2add(s0[p], wa);
                s1[p]  = f2add(s1[p], wb);
                sqa[p] = f2fma(wa, a, sqa[p]);
                sqb[p] = f2fma(wb, b, sqb[p]);
                sr4[p] = f2fma(wa, b, sr4[p]);
            }
        }
        u64 qq[2] = {f2add(sqa[0], sqb[0]), f2add(sqa[1], sqb[1])};

        // publish vertical sums (one STS.128 per field)
        {
            ulonglong2 t;
            t.x = s0[0]; t.y = s0[1];
            *reinterpret_cast<ulonglong2*>(&vsbuf[buf][0][8 + c0]) = t;
            t.x = s1[0]; t.y = s1[1];
            *reinterpret_cast<ulonglong2*>(&vsbuf[buf][1][8 + c0]) = t;
            t.x = qq[0]; t.y = qq[1];
            *reinterpret_cast<ulonglong2*>(&vsbuf[buf][2][8 + c0]) = t;
            t.x = sr4[0]; t.y = sr4[1];
            *reinterpret_cast<ulonglong2*>(&vsbuf[buf][3][8 + c0]) = t;
        }
        __syncthreads();

        // horizontal 11-tap conv, scalar FFMA-imm. Own 4 cols (v[8..11])
        // come from registers; halos via 4 aligned LDS.128 per field.
        // data word for col c is 8+c; left halo cols c0-8..c0-1 -> words
        // c0..c0+7; right halo cols c0+4..c0+11 -> words c0+12..c0+19.
        float cv[4][4];
        u64 own[4][2] = {{s0[0], s0[1]}, {s1[0], s1[1]},
                         {qq[0], qq[1]}, {sr4[0], sr4[1]}};
#pragma unroll
        for (int f = 0; f < 4; ++f) {
            float v[20];
            float4 L0 = *reinterpret_cast<const float4*>(&vsbuf[buf][f][c0]);
            float4 L1 = *reinterpret_cast<const float4*>(&vsbuf[buf][f][c0 + 4]);
            float4 R0 = *reinterpret_cast<const float4*>(&vsbuf[buf][f][c0 + 12]);
            float4 R1 = *reinterpret_cast<const float4*>(&vsbuf[buf][f][c0 + 16]);
            v[0] = L0.x; v[1] = L0.y; v[2] = L0.z; v[3] = L0.w;
            v[4] = L1.x; v[5] = L1.y; v[6] = L1.z; v[7] = L1.w;
            upk2(own[f][0], v[8], v[9]);
            upk2(own[f][1], v[10], v[11]);
            v[12] = R0.x; v[13] = R0.y; v[14] = R0.z; v[15] = R0.w;
            v[16] = R1.x; v[17] = R1.y; v[18] = R1.z; v[19] = R1.w;
#pragma unroll
            for (int j = 0; j < 4; ++j) {
                float s = KW[5] * v[8 + j];
#pragma unroll
                for (int k = 0; k < 11; ++k) {
                    if (k == 5) continue;
                    s += KW[k] * v[3 + j + k];
                }
                cv[f][j] = s;
            }
        }

        // SSIM map, packed (2 cols per pack)
#pragma unroll
        for (int p = 0; p < 2; ++p) {
            u64 m1 = pk2(cv[0][2 * p], cv[0][2 * p + 1]);
            u64 m2 = pk2(cv[1][2 * p], cv[1][2 * p + 1]);
            u64 q2 = pk2(cv[2][2 * p], cv[2][2 * p + 1]);
            u64 rr = pk2(cv[3][2 * p], cv[3][2 * p + 1]);

            u64 m12 = f2mul(m1, m2);
            u64 sms = f2fma(m2, m2, f2mul(m1, m1));       // m1^2 + m2^2
            u64 num1 = f2fma(TWO, m12, C1);               // 2*m12 + c1
            u64 sig12 = f2fma(m12, NEG1, rr);             // r - m12
            u64 num2 = f2fma(TWO, sig12, C2);             // 2*sig12 + c2
            u64 den1 = f2add(sms, C1);
            u64 den2 = f2add(f2fma(sms, NEG1, q2), C2);   // q - sms + c2
            u64 num = f2mul(num1, num2);
            u64 den = f2mul(den1, den2);

            float n0, n1, d0, d1;
            upk2(num, n0, n1);
            upk2(den, d0, d1);
            acc += __fdividef(n0, d0);
            acc += __fdividef(n1, d1);
        }
    }

    // block reduction -> per-block partial
#pragma unroll
    for (int o = 16; o > 0; o >>= 1)
        acc += __shfl_down_sync(0xFFFFFFFFu, acc, o);

    __shared__ float wsum[4];
    __shared__ int is_last;
    if ((tid & 31) == 0) wsum[tid >> 5] = acc;
    __syncthreads();
    if (tid == 0) {
        double s = (double)wsum[0] + (double)wsum[1] + (double)wsum[2] +
                   (double)wsum[3];
        g_partial[blockIdx.y * GX + blockIdx.x] = s;
        __threadfence();
        unsigned old = atomicInc(&g_count, NBLOCKS - 1);  // wraps to 0
        is_last = (old == NBLOCKS - 1);
    }
    __syncthreads();

    // last block finalizes (graph-replay deterministic: counter wraps to 0)
    if (is_last) {
        __threadfence();
        double s = 0.0;
        for (int i = tid; i < NBLOCKS; i += NTHREADS) s += __ldcg(&g_partial[i]);
#pragma unroll
        for (int o = 16; o > 0; o >>= 1)
            s += __shfl_down_sync(0xFFFFFFFFu, s, o);
        __shared__ double dsm[4];
        if ((tid & 31) == 0) dsm[tid >> 5] = s;
        __syncthreads();
        if (tid == 0) {
            double tot = dsm[0] + dsm[1] + dsm[2] + dsm[3];
            out[0] = (float)(1.0 - tot / NPIX);
        }
    }
}

extern "C" void kernel_launch(void* const* d_in, const int* in_sizes, int n_in,
                              void* d_out, int out_size) {
    const float* sr = (const float*)d_in[0];
    const float* hr = (const float*)d_in[1];
    float* out = (float*)d_out;

    dim3 grid(GX, GY);
    ssim_kernel<<<grid, NTHREADS>>>(sr, hr, out);
}